// round 6
// baseline (speedup 1.0000x reference)
#include <cuda_runtime.h>
#include <math.h>

// Problem constants
#define XD 8            // feature dims (XD == ZD == 8)
#define LCH 64          // t-chunk length

// Scratch: per-chunk scan summaries U[c][r], carries C[c][r]
__device__ float g_U[64 * 8192];
__device__ float g_C[64 * 8192];

// ---------------- packed fp32x2 helpers (sm_100a) ----------------
static __device__ __forceinline__ float2 ffma2(float2 a, float2 b, float2 c) {
    float2 d;
    asm("{\n\t"
        ".reg .b64 ra, rb, rc, rd;\n\t"
        "mov.b64 ra, {%2, %3};\n\t"
        "mov.b64 rb, {%4, %5};\n\t"
        "mov.b64 rc, {%6, %7};\n\t"
        "fma.rn.f32x2 rd, ra, rb, rc;\n\t"
        "mov.b64 {%0, %1}, rd;\n\t"
        "}"
        : "=f"(d.x), "=f"(d.y)
        : "f"(a.x), "f"(a.y), "f"(b.x), "f"(b.y), "f"(c.x), "f"(c.y));
    return d;
}

static __device__ __forceinline__ float2 fmul2(float2 a, float2 b) {
    float2 d;
    asm("{\n\t"
        ".reg .b64 ra, rb, rd;\n\t"
        "mov.b64 ra, {%2, %3};\n\t"
        "mov.b64 rb, {%4, %5};\n\t"
        "mul.rn.f32x2 rd, ra, rb;\n\t"
        "mov.b64 {%0, %1}, rd;\n\t"
        "}"
        : "=f"(d.x), "=f"(d.y)
        : "f"(a.x), "f"(a.y), "f"(b.x), "f"(b.y));
    return d;
}

static __device__ __forceinline__ float2 fadd2(float2 a, float2 b) {
    float2 d;
    asm("{\n\t"
        ".reg .b64 ra, rb, rd;\n\t"
        "mov.b64 ra, {%2, %3};\n\t"
        "mov.b64 rb, {%4, %5};\n\t"
        "add.rn.f32x2 rd, ra, rb;\n\t"
        "mov.b64 {%0, %1}, rd;\n\t"
        "}"
        : "=f"(d.x), "=f"(d.y)
        : "f"(a.x), "f"(a.y), "f"(b.x), "f"(b.y));
    return d;
}

static __device__ __forceinline__ float2 splat(float v) { return make_float2(v, v); }

static __device__ __forceinline__ float sigmoidf_(float x) {
    return 1.0f / (1.0f + expf(-x));
}

// ---------------- Kernel 1: per-chunk scan summaries (t-packed) ----------------
// U[c][r] = sum_{s in chunk c} Ghat^{(chunk_end-1-s)} * b_s,  b_s = gamma[r].Z[s]
// lane = one row; b computed as f32x2 over t-pairs; u recurrence scalar.
__global__ __launch_bounds__(128) void dlm_chunk_kernel(
    const float* __restrict__ Z, const float* __restrict__ G,
    const float* __restrict__ gamma, int R)
{
    __shared__ __align__(16) float sZT[XD * 68];   // transposed [d][t], stride 68

    const int c = blockIdx.y;
    const int t0 = c * LCH;
    for (int i = threadIdx.x; i < LCH * XD; i += blockDim.x) {
        const int t = i >> 3, d = i & 7;
        sZT[d * 68 + t] = Z[t0 * XD + i];
    }
    __syncthreads();

    const int warp = threadIdx.x >> 5, lane = threadIdx.x & 31;
    const int r = blockIdx.x * 128 + warp * 32 + lane;

    const float4 q0 = *(const float4*)(gamma + r * XD);
    const float4 q1 = *(const float4*)(gamma + r * XD + 4);
    float2 ga2[XD] = { splat(q0.x), splat(q0.y), splat(q0.z), splat(q0.w),
                       splat(q1.x), splat(q1.y), splat(q1.z), splat(q1.w) };
    const float g = sigmoidf_(G[r]);

    float u = 0.f;
#pragma unroll
    for (int i = 0; i < LCH / 4; ++i) {
        const int tl = i * 4;
        // b for 4 t, split into two 4-deep chains per t-pair
        float2 bl01, bl23, bh01, bh23;
#pragma unroll
        for (int d = 0; d < XD; ++d) {
            const float4 zv = *(const float4*)&sZT[d * 68 + tl];
            const float2 z01 = make_float2(zv.x, zv.y);
            const float2 z23 = make_float2(zv.z, zv.w);
            if (d == 0)      { bl01 = fmul2(ga2[0], z01); bl23 = fmul2(ga2[0], z23); }
            else if (d < 4)  { bl01 = ffma2(ga2[d], z01, bl01); bl23 = ffma2(ga2[d], z23, bl23); }
            else if (d == 4) { bh01 = fmul2(ga2[4], z01); bh23 = fmul2(ga2[4], z23); }
            else             { bh01 = ffma2(ga2[d], z01, bh01); bh23 = ffma2(ga2[d], z23, bh23); }
        }
        const float2 b01 = fadd2(bl01, bh01);
        const float2 b23 = fadd2(bl23, bh23);
        u = fmaf(g, u, b01.x);
        u = fmaf(g, u, b01.y);
        u = fmaf(g, u, b23.x);
        u = fmaf(g, u, b23.y);
    }
    g_U[c * R + r] = u;
}

// ---------------- Kernel 1b: serial prefix over chunk summaries ----------------
// C[0]=0; C[c] = Ghat^LCH * C[c-1] + U[c-1]   (theta at t = c*LCH)
__global__ __launch_bounds__(256) void dlm_carry_kernel(
    const float* __restrict__ G, int R, int NC)
{
    const int r = blockIdx.x * blockDim.x + threadIdx.x;
    if (r >= R) return;
    float g = sigmoidf_(G[r]);
    float gl = g;
#pragma unroll
    for (int s = 0; s < 6; ++s) gl = gl * gl;   // Ghat^64 (LCH=64=2^6)

    float th = 0.f;
#pragma unroll 4
    for (int c = 0; c < NC; ++c) {
        g_C[c * R + r] = th;
        th = fmaf(gl, th, g_U[c * R + r]);
    }
}

// ---------------- Kernel 2: main compute, t-packed f32x2 (R5 winner) ----------------
// lane = one row; f32x2 packs two time steps; coefficient splats hoisted.
// out[r,t] = theta_t + eta[r].X[t] + zeta[r].Z[t]; carry-in from g_C (uniform CTAs).
__global__ __launch_bounds__(128, 4) void dlm_main_kernel(
    const float* __restrict__ X, const float* __restrict__ Z,
    const float* __restrict__ G, const float* __restrict__ eta,
    const float* __restrict__ zeta, const float* __restrict__ gamma,
    float* __restrict__ out, int R, int T)
{
    __shared__ __align__(16) float sXT[XD * 68];   // transposed: [d][t], stride 68
    __shared__ __align__(16) float sZT[XD * 68];
    __shared__ float tile[4][32 * 33];             // per warp: [t_local][row(lane)], stride 33

    const int c = blockIdx.y;
    const int t0 = c * LCH;
    for (int i = threadIdx.x; i < LCH * XD; i += blockDim.x) {
        const int t = i >> 3, d = i & 7;
        sXT[d * 68 + t] = X[t0 * XD + i];
        sZT[d * 68 + t] = Z[t0 * XD + i];
    }
    __syncthreads();

    const int warp = threadIdx.x >> 5, lane = threadIdx.x & 31;
    const int rwbase = blockIdx.x * 128 + warp * 32;
    const int r = rwbase + lane;

    // Hoisted coefficient splats (loop-invariant register pairs)
    const float4 e0 = *(const float4*)(eta  + r * XD);
    const float4 e1 = *(const float4*)(eta  + r * XD + 4);
    const float4 s0 = *(const float4*)(zeta + r * XD);
    const float4 s1 = *(const float4*)(zeta + r * XD + 4);
    const float4 q0 = *(const float4*)(gamma + r * XD);
    const float4 q1 = *(const float4*)(gamma + r * XD + 4);
    float2 et2[XD] = { splat(e0.x), splat(e0.y), splat(e0.z), splat(e0.w),
                       splat(e1.x), splat(e1.y), splat(e1.z), splat(e1.w) };
    float2 ze2[XD] = { splat(s0.x), splat(s0.y), splat(s0.z), splat(s0.w),
                       splat(s1.x), splat(s1.y), splat(s1.z), splat(s1.w) };
    float2 ga2[XD] = { splat(q0.x), splat(q0.y), splat(q0.z), splat(q0.w),
                       splat(q1.x), splat(q1.y), splat(q1.z), splat(q1.w) };

    const float g = sigmoidf_(G[r]);

    // Uniform carry-in — prefix precomputed by dlm_carry_kernel
    float th = __ldg(&g_C[c * R + r]);

    float* mytile = tile[warp];
#pragma unroll
    for (int tb = 0; tb < 2; ++tb) {
#pragma unroll 4
        for (int i = 0; i < 8; ++i) {
            const int tl = tb * 32 + i * 4;        // 4 time steps this iter

            // eta . X  (packed over t-pairs; data pairs are float4 subregisters)
            float2 A01, A23;
            {
                const float4 xv = *(const float4*)&sXT[0 * 68 + tl];
                A01 = fmul2(et2[0], make_float2(xv.x, xv.y));
                A23 = fmul2(et2[0], make_float2(xv.z, xv.w));
            }
#pragma unroll
            for (int d = 1; d < XD; ++d) {
                const float4 xv = *(const float4*)&sXT[d * 68 + tl];
                A01 = ffma2(et2[d], make_float2(xv.x, xv.y), A01);
                A23 = ffma2(et2[d], make_float2(xv.z, xv.w), A23);
            }

            // zeta . Z and gamma . Z (b), sharing the Z loads; b split into two 4-chains
            float2 B01, B23, bl01, bl23, bh01, bh23;
#pragma unroll
            for (int d = 0; d < XD; ++d) {
                const float4 zv = *(const float4*)&sZT[d * 68 + tl];
                const float2 z01 = make_float2(zv.x, zv.y);
                const float2 z23 = make_float2(zv.z, zv.w);
                if (d == 0) { B01 = fmul2(ze2[0], z01); B23 = fmul2(ze2[0], z23);
                              bl01 = fmul2(ga2[0], z01); bl23 = fmul2(ga2[0], z23); }
                else if (d < 4) { B01 = ffma2(ze2[d], z01, B01); B23 = ffma2(ze2[d], z23, B23);
                                  bl01 = ffma2(ga2[d], z01, bl01); bl23 = ffma2(ga2[d], z23, bl23); }
                else if (d == 4) { B01 = ffma2(ze2[d], z01, B01); B23 = ffma2(ze2[d], z23, B23);
                                   bh01 = fmul2(ga2[4], z01); bh23 = fmul2(ga2[4], z23); }
                else { B01 = ffma2(ze2[d], z01, B01); B23 = ffma2(ze2[d], z23, B23);
                       bh01 = ffma2(ga2[d], z01, bh01); bh23 = ffma2(ga2[d], z23, bh23); }
            }
            const float2 xz01 = fadd2(A01, B01);
            const float2 xz23 = fadd2(A23, B23);
            const float2 b01 = fadd2(bl01, bh01);
            const float2 b23 = fadd2(bl23, bh23);

            // Scalar recurrence + output assembly (no pair-construction MOVs)
            const float o0 = th + xz01.x;  th = fmaf(g, th, b01.x);
            const float o1 = th + xz01.y;  th = fmaf(g, th, b01.y);
            const float o2 = th + xz23.x;  th = fmaf(g, th, b23.x);
            const float o3 = th + xz23.y;  th = fmaf(g, th, b23.y);

            const int tt = i * 4;                  // local t within tile
            mytile[(tt + 0) * 33 + lane] = o0;     // bank (t+lane)%32: conflict-free
            mytile[(tt + 1) * 33 + lane] = o1;
            mytile[(tt + 2) * 33 + lane] = o2;
            mytile[(tt + 3) * 33 + lane] = o3;
        }
        __syncwarp();
        // Coalesced writeback: 8 x STG.128 per warp; scalar tile reads bank-bijective
        const int tbase = t0 + tb * 32;
#pragma unroll
        for (int k = 0; k < 8; ++k) {
            const int sid = k * 32 + lane;
            const int row = sid >> 3;              // 0..31
            const int tg  = (sid & 7) << 2;        // 0,4,...,28
            float4 v;
            v.x = mytile[(tg + 0) * 33 + row];
            v.y = mytile[(tg + 1) * 33 + row];
            v.z = mytile[(tg + 2) * 33 + row];
            v.w = mytile[(tg + 3) * 33 + row];
            *(float4*)&out[(rwbase + row) * T + tbase + tg] = v;
        }
        __syncwarp();
    }
}

// ---------------- launch ----------------
extern "C" void kernel_launch(void* const* d_in, const int* in_sizes, int n_in,
                              void* d_out, int out_size) {
    const float* X     = (const float*)d_in[0];   // [T, 8]
    const float* Z     = (const float*)d_in[1];   // [T, 8]
    const float* G     = (const float*)d_in[2];   // [R]
    const float* eta   = (const float*)d_in[3];   // [R, 8]
    const float* zeta  = (const float*)d_in[4];   // [R, 8]
    const float* gamma = (const float*)d_in[5];   // [R, 8]
    float* out = (float*)d_out;                   // [R, T]

    const int T = in_sizes[0] / XD;   // 2048
    const int R = in_sizes[2];        // 4096
    const int NC = T / LCH;           // 32 chunks

    // K1: chunk summaries, t-packed. grid (32, 32), 128 threads.
    dlm_chunk_kernel<<<dim3(R / 128, NC), 128>>>(Z, G, gamma, R);
    // K1b: serial prefix over chunks, 1 thread per row.
    dlm_carry_kernel<<<(R + 255) / 256, 256>>>(G, R, NC);
    // K2: main, t-packed (R5 winner), uniform CTAs. grid (32, 32), 128 threads.
    dlm_main_kernel<<<dim3(R / 128, NC), 128>>>(X, Z, G, eta, zeta, gamma, out, R, T);
}

// round 7
// speedup vs baseline: 1.2701x; 1.2701x over previous
#include <cuda_runtime.h>
#include <math.h>

// Problem constants
#define XD 8            // feature dims (XD == ZD == 8)
#define LCH 64          // t-chunk length

// Scratch: per-chunk scan summaries U[c][r]
__device__ float g_U[64 * 8192];

// ---------------- packed fp32x2 helpers (sm_100a) ----------------
static __device__ __forceinline__ float2 ffma2(float2 a, float2 b, float2 c) {
    float2 d;
    asm("{\n\t"
        ".reg .b64 ra, rb, rc, rd;\n\t"
        "mov.b64 ra, {%2, %3};\n\t"
        "mov.b64 rb, {%4, %5};\n\t"
        "mov.b64 rc, {%6, %7};\n\t"
        "fma.rn.f32x2 rd, ra, rb, rc;\n\t"
        "mov.b64 {%0, %1}, rd;\n\t"
        "}"
        : "=f"(d.x), "=f"(d.y)
        : "f"(a.x), "f"(a.y), "f"(b.x), "f"(b.y), "f"(c.x), "f"(c.y));
    return d;
}

static __device__ __forceinline__ float2 fmul2(float2 a, float2 b) {
    float2 d;
    asm("{\n\t"
        ".reg .b64 ra, rb, rd;\n\t"
        "mov.b64 ra, {%2, %3};\n\t"
        "mov.b64 rb, {%4, %5};\n\t"
        "mul.rn.f32x2 rd, ra, rb;\n\t"
        "mov.b64 {%0, %1}, rd;\n\t"
        "}"
        : "=f"(d.x), "=f"(d.y)
        : "f"(a.x), "f"(a.y), "f"(b.x), "f"(b.y));
    return d;
}

static __device__ __forceinline__ float2 fadd2(float2 a, float2 b) {
    float2 d;
    asm("{\n\t"
        ".reg .b64 ra, rb, rd;\n\t"
        "mov.b64 ra, {%2, %3};\n\t"
        "mov.b64 rb, {%4, %5};\n\t"
        "add.rn.f32x2 rd, ra, rb;\n\t"
        "mov.b64 {%0, %1}, rd;\n\t"
        "}"
        : "=f"(d.x), "=f"(d.y)
        : "f"(a.x), "f"(a.y), "f"(b.x), "f"(b.y));
    return d;
}

static __device__ __forceinline__ float2 splat(float v) { return make_float2(v, v); }

static __device__ __forceinline__ float sigmoidf_(float x) {
    return 1.0f / (1.0f + expf(-x));
}

// Load coefficient row-pair {rA, rB} packed into float2[8]  (K1 only)
static __device__ __forceinline__ void load_pair(const float* __restrict__ base,
                                                 int rA, int rB, float2 o[XD]) {
    const float4 a0 = *(const float4*)(base + rA * XD);
    const float4 a1 = *(const float4*)(base + rA * XD + 4);
    const float4 b0 = *(const float4*)(base + rB * XD);
    const float4 b1 = *(const float4*)(base + rB * XD + 4);
    o[0] = make_float2(a0.x, b0.x); o[1] = make_float2(a0.y, b0.y);
    o[2] = make_float2(a0.z, b0.z); o[3] = make_float2(a0.w, b0.w);
    o[4] = make_float2(a1.x, b1.x); o[5] = make_float2(a1.y, b1.y);
    o[6] = make_float2(a1.z, b1.z); o[7] = make_float2(a1.w, b1.w);
}

static __device__ __forceinline__ float2 compute_b(const float2 ga[XD],
                                                   float4 z0, float4 z1) {
    float2 b0 = fmul2(ga[0], splat(z0.x));
    b0 = ffma2(ga[1], splat(z0.y), b0);
    b0 = ffma2(ga[2], splat(z0.z), b0);
    b0 = ffma2(ga[3], splat(z0.w), b0);
    float2 b1 = fmul2(ga[4], splat(z1.x));
    b1 = ffma2(ga[5], splat(z1.y), b1);
    b1 = ffma2(ga[6], splat(z1.z), b1);
    b1 = ffma2(ga[7], splat(z1.w), b1);
    return fadd2(b0, b1);
}

// ---------------- Kernel 1 (R1/R5-proven): per-chunk scan summaries ----------------
// U[c][r] = sum_{s in chunk c} Ghat^{(chunk_end-1-s)} * b_s
__global__ __launch_bounds__(128) void dlm_chunk_kernel(
    const float* __restrict__ Z, const float* __restrict__ G,
    const float* __restrict__ gamma, int R)
{
    __shared__ __align__(16) float sZ[LCH * XD];
    const int c = blockIdx.y;
    const int t0 = c * LCH;
    for (int i = threadIdx.x; i < LCH * XD; i += blockDim.x)
        sZ[i] = Z[t0 * XD + i];
    __syncthreads();

    const int warp = threadIdx.x >> 5, lane = threadIdx.x & 31;
    const int rbase = blockIdx.x * 256 + warp * 64;
    const int rA = rbase + lane, rB = rA + 32;

    float2 ga[XD];
    load_pair(gamma, rA, rB, ga);
    const float2 g2 = make_float2(sigmoidf_(G[rA]), sigmoidf_(G[rB]));

    float2 u = make_float2(0.f, 0.f);
#pragma unroll 4
    for (int i = 0; i < LCH; ++i) {
        const float4 z0 = *(const float4*)&sZ[i * XD];
        const float4 z1 = *(const float4*)&sZ[i * XD + 4];
        const float2 b = compute_b(ga, z0, z1);
        u = ffma2(g2, u, b);
    }
    g_U[c * R + rA] = u.x;
    g_U[c * R + rB] = u.y;
}

// ---------------- Kernel 2: main compute, t-packed f32x2, batched LDS ----------------
// lane = one row; f32x2 packs two time steps; coefficient splats hoisted.
// All 16 LDS.128 of an iteration issue up-front so the 29-cyc LDS latency is
// covered by the load burst itself; fma chains then run dependency-free.
__global__ __launch_bounds__(128, 3) void dlm_main_kernel(
    const float* __restrict__ X, const float* __restrict__ Z,
    const float* __restrict__ G, const float* __restrict__ eta,
    const float* __restrict__ zeta, const float* __restrict__ gamma,
    float* __restrict__ out, int R, int T)
{
    __shared__ __align__(16) float sXT[XD * 68];   // transposed: [d][t], stride 68
    __shared__ __align__(16) float sZT[XD * 68];
    __shared__ float tile[4][32 * 33];             // per warp: [t_local][row(lane)], stride 33

    const int c = blockIdx.y;
    const int t0 = c * LCH;
    for (int i = threadIdx.x; i < LCH * XD; i += blockDim.x) {
        const int t = i >> 3, d = i & 7;
        sXT[d * 68 + t] = X[t0 * XD + i];
        sZT[d * 68 + t] = Z[t0 * XD + i];
    }
    __syncthreads();

    const int warp = threadIdx.x >> 5, lane = threadIdx.x & 31;
    const int rwbase = blockIdx.x * 128 + warp * 32;
    const int r = rwbase + lane;

    // Hoisted coefficient splats (loop-invariant register pairs)
    const float4 e0 = *(const float4*)(eta  + r * XD);
    const float4 e1 = *(const float4*)(eta  + r * XD + 4);
    const float4 s0 = *(const float4*)(zeta + r * XD);
    const float4 s1 = *(const float4*)(zeta + r * XD + 4);
    const float4 q0 = *(const float4*)(gamma + r * XD);
    const float4 q1 = *(const float4*)(gamma + r * XD + 4);
    float2 et2[XD] = { splat(e0.x), splat(e0.y), splat(e0.z), splat(e0.w),
                       splat(e1.x), splat(e1.y), splat(e1.z), splat(e1.w) };
    float2 ze2[XD] = { splat(s0.x), splat(s0.y), splat(s0.z), splat(s0.w),
                       splat(s1.x), splat(s1.y), splat(s1.z), splat(s1.w) };
    float2 ga2[XD] = { splat(q0.x), splat(q0.y), splat(q0.z), splat(q0.w),
                       splat(q1.x), splat(q1.y), splat(q1.z), splat(q1.w) };

    const float g = sigmoidf_(G[r]);
    float gl = g;
#pragma unroll
    for (int s = 0; s < 6; ++s) gl = gl * gl;      // Ghat^64

    // Carry-in: prefix over previous chunks' summaries (R5-proven; coalesced)
    float th = 0.f;
#pragma unroll 4
    for (int j = 0; j < c; ++j)
        th = fmaf(gl, th, __ldg(&g_U[j * R + r]));

    float* mytile = tile[warp];
#pragma unroll
    for (int tb = 0; tb < 2; ++tb) {
#pragma unroll 2
        for (int i = 0; i < 8; ++i) {
            const int tl = tb * 32 + i * 4;        // 4 time steps this iter

            // ---- batched load burst: 16 x LDS.128, issued back-to-back ----
            float4 xv[XD], zv[XD];
#pragma unroll
            for (int d = 0; d < XD; ++d) xv[d] = *(const float4*)&sXT[d * 68 + tl];
#pragma unroll
            for (int d = 0; d < XD; ++d) zv[d] = *(const float4*)&sZT[d * 68 + tl];

            // ---- eta . X (consumes xv; first result ready by end of burst) ----
            float2 A01 = fmul2(et2[0], make_float2(xv[0].x, xv[0].y));
            float2 A23 = fmul2(et2[0], make_float2(xv[0].z, xv[0].w));
#pragma unroll
            for (int d = 1; d < XD; ++d) {
                A01 = ffma2(et2[d], make_float2(xv[d].x, xv[d].y), A01);
                A23 = ffma2(et2[d], make_float2(xv[d].z, xv[d].w), A23);
            }

            // ---- zeta . Z and gamma . Z (b), sharing zv; b split into two 4-chains ----
            float2 B01, B23, bl01, bl23, bh01, bh23;
#pragma unroll
            for (int d = 0; d < XD; ++d) {
                const float2 z01 = make_float2(zv[d].x, zv[d].y);
                const float2 z23 = make_float2(zv[d].z, zv[d].w);
                if (d == 0) { B01 = fmul2(ze2[0], z01); B23 = fmul2(ze2[0], z23);
                              bl01 = fmul2(ga2[0], z01); bl23 = fmul2(ga2[0], z23); }
                else if (d < 4) { B01 = ffma2(ze2[d], z01, B01); B23 = ffma2(ze2[d], z23, B23);
                                  bl01 = ffma2(ga2[d], z01, bl01); bl23 = ffma2(ga2[d], z23, bl23); }
                else if (d == 4) { B01 = ffma2(ze2[d], z01, B01); B23 = ffma2(ze2[d], z23, B23);
                                   bh01 = fmul2(ga2[4], z01); bh23 = fmul2(ga2[4], z23); }
                else { B01 = ffma2(ze2[d], z01, B01); B23 = ffma2(ze2[d], z23, B23);
                       bh01 = ffma2(ga2[d], z01, bh01); bh23 = ffma2(ga2[d], z23, bh23); }
            }
            const float2 xz01 = fadd2(A01, B01);
            const float2 xz23 = fadd2(A23, B23);
            const float2 b01 = fadd2(bl01, bh01);
            const float2 b23 = fadd2(bl23, bh23);

            // Scalar recurrence + output assembly (no pair-construction MOVs)
            const float o0 = th + xz01.x;  th = fmaf(g, th, b01.x);
            const float o1 = th + xz01.y;  th = fmaf(g, th, b01.y);
            const float o2 = th + xz23.x;  th = fmaf(g, th, b23.x);
            const float o3 = th + xz23.y;  th = fmaf(g, th, b23.y);

            const int tt = i * 4;                  // local t within tile
            mytile[(tt + 0) * 33 + lane] = o0;     // bank (t+lane)%32: conflict-free
            mytile[(tt + 1) * 33 + lane] = o1;
            mytile[(tt + 2) * 33 + lane] = o2;
            mytile[(tt + 3) * 33 + lane] = o3;
        }
        __syncwarp();
        // Coalesced writeback: 8 x STG.128 per warp; scalar tile reads bank-bijective
        const int tbase = t0 + tb * 32;
#pragma unroll
        for (int k = 0; k < 8; ++k) {
            const int sid = k * 32 + lane;
            const int row = sid >> 3;              // 0..31
            const int tg  = (sid & 7) << 2;        // 0,4,...,28
            float4 v;
            v.x = mytile[(tg + 0) * 33 + row];
            v.y = mytile[(tg + 1) * 33 + row];
            v.z = mytile[(tg + 2) * 33 + row];
            v.w = mytile[(tg + 3) * 33 + row];
            *(float4*)&out[(rwbase + row) * T + tbase + tg] = v;
        }
        __syncwarp();
    }
}

// ---------------- launch ----------------
extern "C" void kernel_launch(void* const* d_in, const int* in_sizes, int n_in,
                              void* d_out, int out_size) {
    const float* X     = (const float*)d_in[0];   // [T, 8]
    const float* Z     = (const float*)d_in[1];   // [T, 8]
    const float* G     = (const float*)d_in[2];   // [R]
    const float* eta   = (const float*)d_in[3];   // [R, 8]
    const float* zeta  = (const float*)d_in[4];   // [R, 8]
    const float* gamma = (const float*)d_in[5];   // [R, 8]
    float* out = (float*)d_out;                   // [R, T]

    const int T = in_sizes[0] / XD;   // 2048
    const int R = in_sizes[2];        // 4096
    const int NC = T / LCH;           // 32 chunks

    // K1: chunk summaries (R1/R5-proven shape). grid (16, 32), 128 threads.
    dlm_chunk_kernel<<<dim3(R / 256, NC), 128>>>(Z, G, gamma, R);
    // K2: main, t-packed + batched LDS. grid (32, 32) = 1024 CTAs, 128 threads.
    dlm_main_kernel<<<dim3(R / 128, NC), 128>>>(X, Z, G, eta, zeta, gamma, out, R, T);
}